// round 1
// baseline (speedup 1.0000x reference)
#include <cuda_runtime.h>

#define NB 16
#define NC 64
#define NH 128
#define NW 128
#define NE 8
#define NGH 16

// routing probs, combined weights [b][co][ci][tap], combined bias
__device__ float g_probs[NB][NE];
__device__ float g_wcomb[NB * NC * NC * 9];
__device__ float g_bcomb[NB][NC];

// ---------------------------------------------------------------------------
// Kernel 1: gating. One block per batch. GAP -> MLP(64->16 relu ->8)
// -> softmax -> top2 -> renormalize.
// ---------------------------------------------------------------------------
__global__ void gate_kernel(const float* __restrict__ x,
                            const float* __restrict__ wg1,
                            const float* __restrict__ bg1,
                            const float* __restrict__ wg2,
                            const float* __restrict__ bg2) {
    const int b = blockIdx.x;
    const int tid = threadIdx.x;           // 256 threads
    const int warp = tid >> 5, lane = tid & 31;

    __shared__ float pooled[NC];
    __shared__ float hbuf[NGH];
    __shared__ float logits[NE];

    const float* xb = x + (size_t)b * NC * NH * NW;

    // GAP: one warp per channel, 8 warps loop over 64 channels
    for (int c = warp; c < NC; c += 8) {
        const float* xc = xb + (size_t)c * (NH * NW);
        float s = 0.f;
        for (int i = lane; i < NH * NW; i += 32) s += xc[i];
        #pragma unroll
        for (int o = 16; o > 0; o >>= 1) s += __shfl_xor_sync(0xffffffffu, s, o);
        if (lane == 0) pooled[c] = s * (1.0f / (NH * NW));
    }
    __syncthreads();

    if (tid < NGH) {
        float a = bg1[tid];
        #pragma unroll
        for (int c = 0; c < NC; c++) a += pooled[c] * wg1[c * NGH + tid];
        hbuf[tid] = a > 0.f ? a : 0.f;
    }
    __syncthreads();

    if (tid < NE) {
        float a = bg2[tid];
        #pragma unroll
        for (int g = 0; g < NGH; g++) a += hbuf[g] * wg2[g * NE + tid];
        logits[tid] = a;
    }
    __syncthreads();

    if (tid == 0) {
        float m = -1e30f;
        #pragma unroll
        for (int e = 0; e < NE; e++) m = fmaxf(m, logits[e]);
        float p[NE], s = 0.f;
        #pragma unroll
        for (int e = 0; e < NE; e++) { p[e] = expf(logits[e] - m); s += p[e]; }
        float inv = 1.0f / s;
        #pragma unroll
        for (int e = 0; e < NE; e++) p[e] *= inv;
        // top-2 (strict >, first index wins ties, matching lax.top_k)
        int i1 = 0;
        #pragma unroll
        for (int e = 1; e < NE; e++) if (p[e] > p[i1]) i1 = e;
        int i2 = -1;
        #pragma unroll
        for (int e = 0; e < NE; e++) {
            if (e == i1) continue;
            if (i2 < 0 || p[e] > p[i2]) i2 = e;
        }
        float denom = p[i1] + p[i2] + 1e-8f;
        #pragma unroll
        for (int e = 0; e < NE; e++)
            g_probs[b][e] = (e == i1 || e == i2) ? p[e] / denom : 0.f;
    }
}

// ---------------------------------------------------------------------------
// Kernel 2: fold routing probs into per-batch conv weights + bias.
// w_exp layout [E][Co][Ci][3][3]; g_wcomb layout [b][co][ci][tap].
// ---------------------------------------------------------------------------
__global__ void combine_kernel(const float* __restrict__ w_exp,
                               const float* __restrict__ b_exp) {
    const int idx = blockIdx.x * blockDim.x + threadIdx.x;
    const int total = NB * NC * NC * 9;
    if (idx < total) {
        const int b = idx / (NC * NC * 9);
        const int r = idx - b * (NC * NC * 9);   // co*(NC*9) + ci*9 + tap
        const int co = r / (NC * 9);
        const int r2 = r - co * (NC * 9);        // ci*9 + tap
        float s = 0.f;
        #pragma unroll
        for (int e = 0; e < NE; e++)
            s += g_probs[b][e] * w_exp[((size_t)(e * NC + co) * NC) * 9 + r2];
        g_wcomb[idx] = s;
    }
    if (idx < NB * NC) {
        const int b = idx / NC, c = idx - b * NC;
        float s = 0.f;
        #pragma unroll
        for (int e = 0; e < NE; e++) s += g_probs[b][e] * b_exp[e * NC + c];
        g_bcomb[b][c] = s;
    }
}

// ---------------------------------------------------------------------------
// Kernel 3: per-batch 3x3 SAME conv with fused bias + residual.
// Grid: (16 spatial tiles of 32x32, 8 c_out groups of 8, 16 batches).
// Block: 256 threads = 16x16; each thread computes a 2x2 spatial micro-tile
// for 8 c_out channels (32 accumulators).
// ---------------------------------------------------------------------------
#define TCI 8   // c_in chunk
#define TCO 8   // c_out per block

__global__ __launch_bounds__(256, 2)
void conv_kernel(const float* __restrict__ x) {
    const int tile = blockIdx.x;       // 0..15
    const int cog  = blockIdx.y;       // 0..7
    const int b    = blockIdx.z;       // 0..15
    const int ty = tile >> 2, tx = tile & 3;

    const int tid = threadIdx.x;
    const int py = tid >> 4, px = tid & 15;  // 16x16 threads

    __shared__ float in_s[TCI][34][36];      // padded rows
    __shared__ float w_s[TCO][TCI][9];

    float acc[TCO][2][2];
    #pragma unroll
    for (int co = 0; co < TCO; co++)
        #pragma unroll
        for (int dy = 0; dy < 2; dy++)
            #pragma unroll
            for (int dx = 0; dx < 2; dx++) acc[co][dy][dx] = 0.f;

    const int oy0 = ty * 32 + py * 2;
    const int ox0 = tx * 32 + px * 2;
    const float* xb = x + (size_t)b * NC * NH * NW;
    const float* wb = g_wcomb + (size_t)b * NC * NC * 9;

    for (int cb = 0; cb < NC / TCI; cb++) {
        __syncthreads();
        // stage input tile: TCI channels x 34x34 (zero-padded SAME halo)
        for (int i = tid; i < TCI * 34 * 34; i += 256) {
            const int ci = i / (34 * 34);
            const int rr = i - ci * (34 * 34);
            const int iy = rr / 34, ix = rr - iy * 34;
            const int gy = ty * 32 - 1 + iy;
            const int gx = tx * 32 - 1 + ix;
            float v = 0.f;
            if (gy >= 0 && gy < NH && gx >= 0 && gx < NW)
                v = xb[((size_t)(cb * TCI + ci) * NH + gy) * NW + gx];
            in_s[ci][iy][ix] = v;
        }
        // stage weights: TCO x TCI x 9
        for (int i = tid; i < TCO * TCI * 9; i += 256) {
            const int co = i / (TCI * 9);
            const int r  = i - co * (TCI * 9);           // ci*9+tap
            const int ci = r / 9, tap = r - ci * 9;
            w_s[co][ci][tap] =
                wb[((size_t)(cog * TCO + co) * NC + cb * TCI + ci) * 9 + tap];
        }
        __syncthreads();

        #pragma unroll
        for (int ci = 0; ci < TCI; ci++) {
            float in[4][4];
            #pragma unroll
            for (int dy = 0; dy < 4; dy++)
                #pragma unroll
                for (int dx = 0; dx < 4; dx++)
                    in[dy][dx] = in_s[ci][py * 2 + dy][px * 2 + dx];
            #pragma unroll
            for (int co = 0; co < TCO; co++) {
                #pragma unroll
                for (int t = 0; t < 9; t++) {
                    const int ky = t / 3, kx = t - ky * 3;
                    const float w = w_s[co][ci][t];
                    acc[co][0][0] = fmaf(in[ky    ][kx    ], w, acc[co][0][0]);
                    acc[co][0][1] = fmaf(in[ky    ][kx + 1], w, acc[co][0][1]);
                    acc[co][1][0] = fmaf(in[ky + 1][kx    ], w, acc[co][1][0]);
                    acc[co][1][1] = fmaf(in[ky + 1][kx + 1], w, acc[co][1][1]);
                }
            }
        }
    }

    // epilogue: bias + residual, write out
    float* out = nullptr;  // set via launch param trick below
    // (out passed through second kernel arg)
    (void)out;
    extern __shared__ float dummy[]; (void)dummy;
    // note: actual out pointer is a kernel parameter; see signature change.
    // -- replaced below --
}

// Re-declare conv kernel properly with out parameter (the above placeholder
// epilogue comment is resolved here; single definitive kernel):
__global__ __launch_bounds__(256, 2)
void conv_kernel2(const float* __restrict__ x, float* __restrict__ out) {
    const int tile = blockIdx.x;
    const int cog  = blockIdx.y;
    const int b    = blockIdx.z;
    const int ty = tile >> 2, tx = tile & 3;

    const int tid = threadIdx.x;
    const int py = tid >> 4, px = tid & 15;

    __shared__ float in_s[TCI][34][36];
    __shared__ float w_s[TCO][TCI][9];

    float acc[TCO][2][2];
    #pragma unroll
    for (int co = 0; co < TCO; co++)
        #pragma unroll
        for (int dy = 0; dy < 2; dy++)
            #pragma unroll
            for (int dx = 0; dx < 2; dx++) acc[co][dy][dx] = 0.f;

    const int oy0 = ty * 32 + py * 2;
    const int ox0 = tx * 32 + px * 2;
    const float* xb = x + (size_t)b * NC * NH * NW;
    const float* wb = g_wcomb + (size_t)b * NC * NC * 9;

    for (int cb = 0; cb < NC / TCI; cb++) {
        __syncthreads();
        for (int i = tid; i < TCI * 34 * 34; i += 256) {
            const int ci = i / (34 * 34);
            const int rr = i - ci * (34 * 34);
            const int iy = rr / 34, ix = rr - iy * 34;
            const int gy = ty * 32 - 1 + iy;
            const int gx = tx * 32 - 1 + ix;
            float v = 0.f;
            if (gy >= 0 && gy < NH && gx >= 0 && gx < NW)
                v = xb[((size_t)(cb * TCI + ci) * NH + gy) * NW + gx];
            in_s[ci][iy][ix] = v;
        }
        for (int i = tid; i < TCO * TCI * 9; i += 256) {
            const int co = i / (TCI * 9);
            const int r  = i - co * (TCI * 9);
            const int ci = r / 9, tap = r - ci * 9;
            w_s[co][ci][tap] =
                wb[((size_t)(cog * TCO + co) * NC + cb * TCI + ci) * 9 + tap];
        }
        __syncthreads();

        #pragma unroll
        for (int ci = 0; ci < TCI; ci++) {
            float in[4][4];
            #pragma unroll
            for (int dy = 0; dy < 4; dy++)
                #pragma unroll
                for (int dx = 0; dx < 4; dx++)
                    in[dy][dx] = in_s[ci][py * 2 + dy][px * 2 + dx];
            #pragma unroll
            for (int co = 0; co < TCO; co++) {
                #pragma unroll
                for (int t = 0; t < 9; t++) {
                    const int ky = t / 3, kx = t - ky * 3;
                    const float w = w_s[co][ci][t];
                    acc[co][0][0] = fmaf(in[ky    ][kx    ], w, acc[co][0][0]);
                    acc[co][0][1] = fmaf(in[ky    ][kx + 1], w, acc[co][0][1]);
                    acc[co][1][0] = fmaf(in[ky + 1][kx    ], w, acc[co][1][0]);
                    acc[co][1][1] = fmaf(in[ky + 1][kx + 1], w, acc[co][1][1]);
                }
            }
        }
    }

    #pragma unroll
    for (int co = 0; co < TCO; co++) {
        const int cg = cog * TCO + co;
        const float bias = g_bcomb[b][cg];
        #pragma unroll
        for (int dy = 0; dy < 2; dy++)
            #pragma unroll
            for (int dx = 0; dx < 2; dx++) {
                const int oy = oy0 + dy, ox = ox0 + dx;
                const size_t o = ((size_t)(b * NC + cg) * NH + oy) * NW + ox;
                out[o] = acc[co][dy][dx] + bias + x[o];
            }
    }
}

extern "C" void kernel_launch(void* const* d_in, const int* in_sizes, int n_in,
                              void* d_out, int out_size) {
    const float* x     = (const float*)d_in[0];
    const float* wg1   = (const float*)d_in[1];
    const float* bg1   = (const float*)d_in[2];
    const float* wg2   = (const float*)d_in[3];
    const float* bg2   = (const float*)d_in[4];
    const float* w_exp = (const float*)d_in[5];
    const float* b_exp = (const float*)d_in[6];
    float* out = (float*)d_out;

    gate_kernel<<<NB, 256>>>(x, wg1, bg1, wg2, bg2);

    const int total = NB * NC * NC * 9;
    combine_kernel<<<(total + 255) / 256, 256>>>(w_exp, b_exp);

    dim3 grid(16, NC / TCO, NB);
    conv_kernel2<<<grid, 256>>>(x, out);
}

// round 3
// speedup vs baseline: 1.0600x; 1.0600x over previous
#include <cuda_runtime.h>

#define NB 16
#define NC 64
#define NH 128
#define NW 128
#define NE 8
#define NGH 16

__device__ float g_pooled[NB * NC];
__device__ float g_probs[NB][NE];
__device__ float g_wcomb[NB * NC * NC * 9];
__device__ float g_bcomb[NB][NC];

// f32x2 packed helpers (sm_103a FFMA2 path — only reachable via PTX)
#define PACK2(d, lo, hi) \
    asm("mov.b64 %0, {%1, %2};" : "=l"(d) : "f"(lo), "f"(hi))
#define UNPACK2(lo, hi, d) \
    asm("mov.b64 {%0, %1}, %2;" : "=f"(lo), "=f"(hi) : "l"(d))
#define FMA2(d, a, b) \
    asm("fma.rn.f32x2 %0, %1, %2, %0;" : "+l"(d) : "l"(a), "l"(b))

// ---------------------------------------------------------------------------
// Kernel 1a: parallel GAP. One block per (b, c): 1024 blocks.
// ---------------------------------------------------------------------------
__global__ __launch_bounds__(256)
void pool_kernel(const float* __restrict__ x) {
    const int bc = blockIdx.x;
    const int tid = threadIdx.x;
    const float4* p4 = (const float4*)(x + (size_t)bc * NH * NW);

    float s = 0.f;
    #pragma unroll 4
    for (int i = tid; i < (NH * NW) / 4; i += 256) {
        float4 v = p4[i];
        s += (v.x + v.y) + (v.z + v.w);
    }
    #pragma unroll
    for (int o = 16; o > 0; o >>= 1) s += __shfl_xor_sync(0xffffffffu, s, o);

    __shared__ float ws[8];
    if ((tid & 31) == 0) ws[tid >> 5] = s;
    __syncthreads();
    if (tid == 0) {
        float t = 0.f;
        #pragma unroll
        for (int w = 0; w < 8; w++) t += ws[w];
        g_pooled[bc] = t * (1.0f / (NH * NW));
    }
}

// ---------------------------------------------------------------------------
// Kernel 1b: gating MLP + softmax + top-2. One block per batch (tiny).
// ---------------------------------------------------------------------------
__global__ void gate_kernel(const float* __restrict__ wg1,
                            const float* __restrict__ bg1,
                            const float* __restrict__ wg2,
                            const float* __restrict__ bg2) {
    const int b = blockIdx.x;
    const int tid = threadIdx.x;  // 64 threads

    __shared__ float pooled[NC];
    __shared__ float hbuf[NGH];
    __shared__ float logits[NE];

    if (tid < NC) pooled[tid] = g_pooled[b * NC + tid];
    __syncthreads();

    if (tid < NGH) {
        float a = bg1[tid];
        #pragma unroll
        for (int c = 0; c < NC; c++) a += pooled[c] * wg1[c * NGH + tid];
        hbuf[tid] = a > 0.f ? a : 0.f;
    }
    __syncthreads();

    if (tid < NE) {
        float a = bg2[tid];
        #pragma unroll
        for (int g = 0; g < NGH; g++) a += hbuf[g] * wg2[g * NE + tid];
        logits[tid] = a;
    }
    __syncthreads();

    if (tid == 0) {
        float m = -1e30f;
        #pragma unroll
        for (int e = 0; e < NE; e++) m = fmaxf(m, logits[e]);
        float p[NE], s = 0.f;
        #pragma unroll
        for (int e = 0; e < NE; e++) { p[e] = expf(logits[e] - m); s += p[e]; }
        float inv = 1.0f / s;
        #pragma unroll
        for (int e = 0; e < NE; e++) p[e] *= inv;
        int i1 = 0;
        #pragma unroll
        for (int e = 1; e < NE; e++) if (p[e] > p[i1]) i1 = e;
        int i2 = -1;
        #pragma unroll
        for (int e = 0; e < NE; e++) {
            if (e == i1) continue;
            if (i2 < 0 || p[e] > p[i2]) i2 = e;
        }
        float denom = p[i1] + p[i2] + 1e-8f;
        #pragma unroll
        for (int e = 0; e < NE; e++)
            g_probs[b][e] = (e == i1 || e == i2) ? p[e] / denom : 0.f;
    }
}

// ---------------------------------------------------------------------------
// Kernel 2: fold routing probs into per-batch conv weights + bias.
// ---------------------------------------------------------------------------
__global__ void combine_kernel(const float* __restrict__ w_exp,
                               const float* __restrict__ b_exp) {
    const int idx = blockIdx.x * blockDim.x + threadIdx.x;
    const int total = NB * NC * NC * 9;
    if (idx < total) {
        const int b = idx / (NC * NC * 9);
        const int r = idx - b * (NC * NC * 9);   // co*(NC*9) + ci*9 + tap
        const int co = r / (NC * 9);
        const int r2 = r - co * (NC * 9);        // ci*9 + tap
        float s = 0.f;
        #pragma unroll
        for (int e = 0; e < NE; e++)
            s += g_probs[b][e] * w_exp[((size_t)(e * NC + co) * NC) * 9 + r2];
        g_wcomb[idx] = s;
    }
    if (idx < NB * NC) {
        const int b = idx / NC, c = idx - b * NC;
        float s = 0.f;
        #pragma unroll
        for (int e = 0; e < NE; e++) s += g_probs[b][e] * b_exp[e * NC + c];
        g_bcomb[b][c] = s;
    }
}

// ---------------------------------------------------------------------------
// Kernel 3: per-batch 3x3 SAME conv, fused bias + residual, f32x2 FMA.
// Grid: (16 spatial tiles of 32x32, 8 c_out groups of 8, 16 batches).
// Block: 256 threads = 16x16; each thread: 2x2 spatial x 8 c_out,
// accumulated as 8x2 packed f32x2 pairs along x.
// ---------------------------------------------------------------------------
#define TCI 8
#define TCO 8

__global__ __launch_bounds__(256, 2)
void conv_kernel(const float* __restrict__ x, float* __restrict__ out) {
    const int tile = blockIdx.x;
    const int cog  = blockIdx.y;
    const int b    = blockIdx.z;
    const int ty = tile >> 2, tx = tile & 3;

    const int tid = threadIdx.x;
    const int py = tid >> 4, px = tid & 15;

    __shared__ float  in_s[TCI][34][36];          // row stride 144B (8B aligned)
    __shared__ float2 w2_s[TCO][TCI][9];          // duplicated weights {w,w}

    unsigned long long acc2[TCO][2];              // {dx0, dx1} per (co, dy)
    #pragma unroll
    for (int co = 0; co < TCO; co++) {
        acc2[co][0] = 0ull;
        acc2[co][1] = 0ull;
    }

    const int oy0 = ty * 32 + py * 2;
    const int ox0 = tx * 32 + px * 2;
    const float* xb = x + (size_t)b * NC * NH * NW;
    const float* wb = g_wcomb + (size_t)b * NC * NC * 9;

    for (int cb = 0; cb < NC / TCI; cb++) {
        __syncthreads();
        // stage input tile: TCI channels x 34x34 (zero-padded halo)
        for (int i = tid; i < TCI * 34 * 34; i += 256) {
            const int ci = i / (34 * 34);
            const int rr = i - ci * (34 * 34);
            const int iy = rr / 34, ix = rr - iy * 34;
            const int gy = ty * 32 - 1 + iy;
            const int gx = tx * 32 - 1 + ix;
            float v = 0.f;
            if (gy >= 0 && gy < NH && gx >= 0 && gx < NW)
                v = xb[((size_t)(cb * TCI + ci) * NH + gy) * NW + gx];
            in_s[ci][iy][ix] = v;
        }
        // stage duplicated weights
        for (int i = tid; i < TCO * TCI * 9; i += 256) {
            const int co = i / (TCI * 9);
            const int r  = i - co * (TCI * 9);
            const int ci = r / 9, tap = r - ci * 9;
            const float v =
                wb[((size_t)(cog * TCO + co) * NC + cb * TCI + ci) * 9 + tap];
            w2_s[co][ci][tap] = make_float2(v, v);
        }
        __syncthreads();

        #pragma unroll
        for (int ci = 0; ci < TCI; ci++) {
            // load 4x4 input window, build shifted packed pairs
            float in[4][4];
            #pragma unroll
            for (int r = 0; r < 4; r++)
                #pragma unroll
                for (int c = 0; c < 4; c++)
                    in[r][c] = in_s[ci][py * 2 + r][px * 2 + c];

            unsigned long long P[4][3];
            #pragma unroll
            for (int r = 0; r < 4; r++)
                #pragma unroll
                for (int k = 0; k < 3; k++)
                    PACK2(P[r][k], in[r][k], in[r][k + 1]);

            #pragma unroll
            for (int co = 0; co < TCO; co++) {
                const unsigned long long* wp =
                    (const unsigned long long*)&w2_s[co][ci][0];
                #pragma unroll
                for (int t = 0; t < 9; t++) {
                    const int ky = t / 3, kx = t - ky * 3;
                    const unsigned long long w2 = wp[t];   // LDS.64 broadcast
                    FMA2(acc2[co][0], P[ky    ][kx], w2);
                    FMA2(acc2[co][1], P[ky + 1][kx], w2);
                }
            }
        }
    }

    // epilogue: bias + residual, 64-bit stores
    #pragma unroll
    for (int co = 0; co < TCO; co++) {
        const int cg = cog * TCO + co;
        const float bias = g_bcomb[b][cg];
        #pragma unroll
        for (int dy = 0; dy < 2; dy++) {
            const int oy = oy0 + dy;
            const size_t o = ((size_t)(b * NC + cg) * NH + oy) * NW + ox0;
            float a0, a1;
            UNPACK2(a0, a1, acc2[co][dy]);
            const float2 res = *(const float2*)(x + o);
            float2 v;
            v.x = a0 + bias + res.x;
            v.y = a1 + bias + res.y;
            *(float2*)(out + o) = v;
        }
    }
}

extern "C" void kernel_launch(void* const* d_in, const int* in_sizes, int n_in,
                              void* d_out, int out_size) {
    const float* x     = (const float*)d_in[0];
    const float* wg1   = (const float*)d_in[1];
    const float* bg1   = (const float*)d_in[2];
    const float* wg2   = (const float*)d_in[3];
    const float* bg2   = (const float*)d_in[4];
    const float* w_exp = (const float*)d_in[5];
    const float* b_exp = (const float*)d_in[6];
    float* out = (float*)d_out;

    pool_kernel<<<NB * NC, 256>>>(x);
    gate_kernel<<<NB, 64>>>(wg1, bg1, wg2, bg2);

    const int total = NB * NC * NC * 9;
    combine_kernel<<<(total + 255) / 256, 256>>>(w_exp, b_exp);

    dim3 grid(16, NC / TCO, NB);
    conv_kernel<<<grid, 256>>>(x, out);
}